// round 9
// baseline (speedup 1.0000x reference)
#include <cuda_runtime.h>

#define HH 128
#define WW 128
#define BB 4
#define CIN 64
#define COUT 64
#define OC1 18

// ---------------- scratch (no allocation allowed) ----------------
__device__ __align__(16) float g_xnhwc[BB*HH*WW*CIN];   // x in NHWC
__device__ __align__(16) float g_off9 [BB*HH*WW*9];     // raw conv1 out, channels 0..8
__device__ __align__(16) float g_wt1p [9*CIN*24];       // conv1 weights [tap][ci][6grp][4] (oc=3g+j, padded)
__device__ __align__(16) float g_wt2  [9*CIN*COUT];     // conv2 weights [k][ci][co]
__device__ float g_stats1[BB*9*2];                      // GN1 sum/sumsq per (b,group)
__device__ float g_stats2[BB*16*2];                     // GN2 sum/sumsq per (b,group)
__device__ float g_sc1[BB*9],  g_sh1[BB*9];             // GN1 per-channel scale/shift
__device__ float g_sc2[BB*COUT], g_sh2[BB*COUT];        // GN2 per-channel scale/shift

// ---------------- K: zero stats ----------------
__global__ void k_zero_stats() {
    int t = threadIdx.x;
    if (t < BB*9*2)  g_stats1[t] = 0.f;
    if (t < BB*16*2) g_stats2[t] = 0.f;
}

// ---------------- K: transpose x NCHW -> NHWC ----------------
__global__ void k_transpose_x(const float* __restrict__ x) {
    __shared__ float tile[32][33];
    int b  = blockIdx.z;
    int p0 = blockIdx.x * 32;
    int c0 = blockIdx.y * 32;
    int tx = threadIdx.x, ty = threadIdx.y;   // 32 x 8
    const float* xb = x + (size_t)b*CIN*HH*WW;
    #pragma unroll
    for (int i = 0; i < 32; i += 8)
        tile[ty+i][tx] = xb[(c0+ty+i)*(HH*WW) + p0 + tx];
    __syncthreads();
    float* ob = g_xnhwc + (size_t)b*HH*WW*CIN;
    #pragma unroll
    for (int i = 0; i < 32; i += 8)
        ob[(size_t)(p0+ty+i)*CIN + c0 + tx] = tile[tx][ty+i];
}

// ---------------- K: prep weights ----------------
__global__ void k_prep_w(const float* __restrict__ w_off, const float* __restrict__ w_dsc) {
    int t = blockIdx.x*blockDim.x + threadIdx.x;
    // g_wt1p: [tap][ci][g][4] with oc = 3g+j (j<3), pad j==3
    if (t < 9*CIN*24) {
        int tap = t / (CIN*24); int r = t % (CIN*24);
        int ci = r / 24; int gj = r % 24;
        int g = gj >> 2, j = gj & 3;
        int oc = g*3 + j;
        float v = 0.f;
        if (j < 3 && oc < OC1)
            v = w_off[oc*(CIN*9) + ci*9 + tap];        // w_off (18,64,3,3)
        g_wt1p[t] = v;
    }
    if (t < 9*CIN*COUT) {
        int k = t / (CIN*COUT); int r = t % (CIN*COUT);
        int ci = r / COUT; int co = r % COUT;
        g_wt2[t] = w_dsc[co*(CIN*9) + ci*9 + k];       // w_dsc (64,64,9,1) -> [k][ci][co]
    }
}

// ---------------- K: conv1 3x3 (64->18) + GN1 stats ----------------
// grid: B*H (full 128-px rows), 192 threads: tx(0..31)->4px, ty(0..5)->3oc
// weights via warp-broadcast __ldg (L1-resident, ty constant per warp) -> no weight smem
__global__ __launch_bounds__(192) void k_conv1(const float* __restrict__ b_off) {
    __shared__ __align__(16) float xs[CIN*132];      // [ci][i], i=0..129 <-> w = i-1
    __shared__ float ssum[9], ssq[9];
    int t = threadIdx.x;
    int tx = t & 31, ty = t >> 5;
    int blk = blockIdx.x;
    int h   = blk & (HH-1);
    int b   = blk >> 7;
    if (t < 9) { ssum[t] = 0.f; ssq[t] = 0.f; }

    float acc[4][3];
    #pragma unroll
    for (int p=0;p<4;p++)
        #pragma unroll
        for (int j=0;j<3;j++) acc[p][j]=0.f;

    const float* xb = g_xnhwc + (size_t)b*(HH*WW*CIN);

    for (int dy = 0; dy < 3; dy++) {
        int y = h + dy - 1;
        __syncthreads();
        // stage one input row (130 positions x 64 ci), zero-padded
        for (int idx = t; idx < 130*16; idx += 192) {
            int pp = idx >> 4;       // i = pp, w = pp-1
            int q  = idx & 15;
            int w  = pp - 1;
            float4 v = make_float4(0.f,0.f,0.f,0.f);
            if ((unsigned)y < HH && (unsigned)w < WW)
                v = *(const float4*)(xb + ((size_t)y*WW + w)*CIN + q*4);
            xs[(q*4+0)*132 + pp] = v.x;
            xs[(q*4+1)*132 + pp] = v.y;
            xs[(q*4+2)*132 + pp] = v.z;
            xs[(q*4+3)*132 + pp] = v.w;
        }
        __syncthreads();
        // weights: [tap][ci][6grp][4] as float4; per warp one broadcast address
        const float4* wdy = (const float4*)(g_wt1p + dy*3*CIN*24) + ty;
        #pragma unroll 2
        for (int ci = 0; ci < CIN; ci++) {
            const float4* ap = (const float4*)(xs + ci*132 + tx*4);
            float4 A0 = ap[0], A1 = ap[1];
            float af[8] = {A0.x,A0.y,A0.z,A0.w,A1.x,A1.y,A1.z,A1.w};
            #pragma unroll
            for (int dx = 0; dx < 3; dx++) {
                float4 wv = __ldg(wdy + (dx*CIN + ci)*6);
                #pragma unroll
                for (int p = 0; p < 4; p++) {
                    float a = af[p+dx];
                    acc[p][0] += a*wv.x;
                    acc[p][1] += a*wv.y;
                    acc[p][2] += a*wv.z;
                }
            }
        }
    }
    __syncthreads();
    // epilogue: bias, store first 9 channels, GN1 stats (group = oc>>1)
    #pragma unroll
    for (int j = 0; j < 3; j++) {
        int oc = ty*3 + j;
        float bia = b_off[oc];
        float s = 0.f, sq = 0.f;
        #pragma unroll
        for (int p = 0; p < 4; p++) {
            float r = acc[p][j] + bia;
            s += r; sq += r*r;
            if (oc < 9)
                g_off9[(((size_t)b*HH + h)*WW + (tx*4 + p))*9 + oc] = r;
        }
        atomicAdd(&ssum[oc>>1], s);
        atomicAdd(&ssq [oc>>1], sq);
    }
    __syncthreads();
    if (t < 9) {
        atomicAdd(&g_stats1[(b*9 + t)*2 + 0], ssum[t]);
        atomicAdd(&g_stats1[(b*9 + t)*2 + 1], ssq[t]);
    }
}

// ---------------- K: finalize GN1 ----------------
__global__ void k_finalize1(const float* __restrict__ g_gn_off, const float* __restrict__ b_gn_off) {
    int t = threadIdx.x;
    if (t >= BB*9) return;
    int b = t / 9, c = t % 9, g = c >> 1;
    float N  = 2.f*HH*WW;
    float mu = g_stats1[(b*9+g)*2+0] / N;
    float var= g_stats1[(b*9+g)*2+1] / N - mu*mu;
    float inv= rsqrtf(var + 1e-5f);
    float sc = g_gn_off[c] * inv;
    g_sc1[t] = sc;
    g_sh1[t] = b_gn_off[c] - mu * sc;
}

// ---------------- K: main fused (offsets -> sample -> GEMM -> raw out + GN2 stats) ----------------
// grid: B*H*2 (64-px half-rows), 256 threads: 16x16, 4px x 4co micro-tile (round-6 proven)
__global__ __launch_bounds__(256) void k_main(const float* __restrict__ b_dsc, float* __restrict__ out) {
    __shared__ __align__(16) float S [CIN*68];    // samples [ci][px(68 pad)]
    __shared__ __align__(16) float Wc[CIN*COUT];  // weight chunk [ci][co]
    __shared__ int   cy0[9*64];
    __shared__ float cwy[9*64];
    __shared__ float sgrp[32];

    int t    = threadIdx.x;
    int blk  = blockIdx.x;
    int half = blk & 1;
    int h    = (blk >> 1) & (HH-1);
    int b    = blk >> 8;
    int w0   = half * 64;

    if (t < 32) sgrp[t] = 0.f;

    // ---- prologue: per-pixel offsets -> tanh -> cumsum -> coords ----
    if (t < 64) {
        int px = t;
        int w  = w0 + px;
        const float* op = g_off9 + (((size_t)b*HH + h)*WW + w)*9;
        float y[9];
        #pragma unroll
        for (int c = 0; c < 9; c++)
            y[c] = tanhf(op[c]*g_sc1[b*9+c] + g_sh1[b*9+c]);
        float o[9];
        o[4]=0.f;
        o[3]=y[3]; o[2]=y[2]+o[3]; o[1]=y[1]+o[2]; o[0]=y[0]+o[1];
        o[5]=y[5]; o[6]=o[5]+y[6]; o[7]=o[6]+y[7]; o[8]=o[7]+y[8];
        #pragma unroll
        for (int k = 0; k < 9; k++) {
            float yc  = fminf(fmaxf((float)h + o[k], 0.f), (float)(HH-1));
            float y0f = floorf(yc);
            cy0[k*64+px] = (int)y0f;
            cwy[k*64+px] = yc - y0f;
        }
    }

    int tx = t & 15, ty = t >> 4;
    float acc[4][4];
    #pragma unroll
    for (int i=0;i<4;i++)
        #pragma unroll
        for (int j=0;j<4;j++) acc[i][j]=0.f;

    int spx = t >> 2;            // sampling: one px per 4 threads
    int c4  = (t & 3) * 16;      // each thread: 16 channels
    const float* xb = g_xnhwc + (size_t)b*(HH*WW*CIN);

    for (int k = 0; k < 9; k++) {
        __syncthreads();
        // stage weight chunk [64ci][64co] (coalesced, pre-transposed)
        {
            const float4* wsrc = (const float4*)(g_wt2 + k*CIN*COUT);
            float4* wdst = (float4*)Wc;
            #pragma unroll
            for (int i = 0; i < 4; i++)
                wdst[t + i*256] = wsrc[t + i*256];
        }
        // build sample chunk: vertical 2-point lerp (x-coord is exact integer)
        {
            int w  = w0 + spx;
            int x0 = min(max(w + k - 4, 0), WW-1);
            int y0 = cy0[k*64 + spx];
            float wy = cwy[k*64 + spx];
            int y1 = min(y0 + 1, HH-1);
            const float* p0 = xb + ((size_t)y0*WW + x0)*CIN + c4;
            const float* p1 = xb + ((size_t)y1*WW + x0)*CIN + c4;
            #pragma unroll
            for (int q = 0; q < 4; q++) {
                float4 v0 = *(const float4*)(p0 + q*4);
                float4 v1 = *(const float4*)(p1 + q*4);
                int ci = c4 + q*4;
                S[(ci+0)*68 + spx] = v0.x + wy*(v1.x - v0.x);
                S[(ci+1)*68 + spx] = v0.y + wy*(v1.y - v0.y);
                S[(ci+2)*68 + spx] = v0.z + wy*(v1.z - v0.z);
                S[(ci+3)*68 + spx] = v0.w + wy*(v1.w - v0.w);
            }
        }
        __syncthreads();
        // SGEMM accumulate over this 64-ci chunk: 2 LDS.128 + 16 FFMA per ci
        #pragma unroll 2
        for (int ci = 0; ci < CIN; ci++) {
            float4 av = *(const float4*)(S + ci*68 + ty*4);     // broadcast
            float4 bb = *(const float4*)(Wc + ci*COUT + tx*4);
            acc[0][0]+=av.x*bb.x; acc[0][1]+=av.x*bb.y; acc[0][2]+=av.x*bb.z; acc[0][3]+=av.x*bb.w;
            acc[1][0]+=av.y*bb.x; acc[1][1]+=av.y*bb.y; acc[1][2]+=av.y*bb.z; acc[1][3]+=av.y*bb.w;
            acc[2][0]+=av.z*bb.x; acc[2][1]+=av.z*bb.y; acc[2][2]+=av.z*bb.z; acc[2][3]+=av.z*bb.w;
            acc[3][0]+=av.w*bb.x; acc[3][1]+=av.w*bb.y; acc[3][2]+=av.w*bb.z; acc[3][3]+=av.w*bb.w;
        }
    }
    __syncthreads();
    // epilogue: bias, raw store (NCHW), GN2 stats (co group == tx)
    float4 bia = *(const float4*)(b_dsc + tx*4);
    float s = 0.f, sq = 0.f;
    #pragma unroll
    for (int i = 0; i < 4; i++) {
        int w = w0 + ty*4 + i;
        float r0 = acc[i][0] + bia.x;
        float r1 = acc[i][1] + bia.y;
        float r2 = acc[i][2] + bia.z;
        float r3 = acc[i][3] + bia.w;
        out[(((size_t)b*COUT + tx*4+0)*HH + h)*WW + w] = r0;
        out[(((size_t)b*COUT + tx*4+1)*HH + h)*WW + w] = r1;
        out[(((size_t)b*COUT + tx*4+2)*HH + h)*WW + w] = r2;
        out[(((size_t)b*COUT + tx*4+3)*HH + h)*WW + w] = r3;
        s  += r0+r1+r2+r3;
        sq += r0*r0 + r1*r1 + r2*r2 + r3*r3;
    }
    atomicAdd(&sgrp[tx*2+0], s);
    atomicAdd(&sgrp[tx*2+1], sq);
    __syncthreads();
    if (t < 32) atomicAdd(&g_stats2[b*32 + t], sgrp[t]);
}

// ---------------- K: finalize GN2 ----------------
__global__ void k_finalize2(const float* __restrict__ g_gn, const float* __restrict__ b_gn) {
    int t = threadIdx.x;
    if (t >= BB*COUT) return;
    int b = t >> 6, co = t & 63, g = co >> 2;
    float N  = 4.f*HH*WW;
    float mu = g_stats2[(b*16+g)*2+0] / N;
    float var= g_stats2[(b*16+g)*2+1] / N - mu*mu;
    float inv= rsqrtf(var + 1e-5f);
    float sc = g_gn[co] * inv;
    g_sc2[t] = sc;
    g_sh2[t] = b_gn[co] - mu * sc;
}

// ---------------- K: normalize + relu in place ----------------
__global__ void k_norm_relu(float* __restrict__ out) {
    int idx = blockIdx.x*blockDim.x + threadIdx.x;   // float4 index
    int e  = idx << 2;
    int bc = e >> 14;                                 // b*64+co
    float sc = g_sc2[bc], sh = g_sh2[bc];
    float4 v = ((float4*)out)[idx];
    v.x = fmaxf(v.x*sc + sh, 0.f);
    v.y = fmaxf(v.y*sc + sh, 0.f);
    v.z = fmaxf(v.z*sc + sh, 0.f);
    v.w = fmaxf(v.w*sc + sh, 0.f);
    ((float4*)out)[idx] = v;
}

// ---------------- launch ----------------
extern "C" void kernel_launch(void* const* d_in, const int* in_sizes, int n_in,
                              void* d_out, int out_size) {
    const float* x        = (const float*)d_in[0];
    const float* w_off    = (const float*)d_in[1];
    const float* b_off    = (const float*)d_in[2];
    const float* g_gn_off = (const float*)d_in[3];
    const float* b_gn_off = (const float*)d_in[4];
    const float* w_dsc    = (const float*)d_in[5];
    const float* b_dsc    = (const float*)d_in[6];
    const float* g_gn     = (const float*)d_in[7];
    const float* b_gn     = (const float*)d_in[8];
    float* out = (float*)d_out;

    k_zero_stats<<<1,128>>>();
    k_transpose_x<<<dim3(512,2,4), dim3(32,8)>>>(x);
    k_prep_w<<<144,256>>>(w_off, w_dsc);
    k_conv1<<<BB*HH, 192>>>(b_off);
    k_finalize1<<<1,64>>>(g_gn_off, b_gn_off);
    k_main<<<BB*HH*2, 256>>>(b_dsc, out);
    k_finalize2<<<1,256>>>(g_gn, b_gn);
    k_norm_relu<<<4096,256>>>(out);
}

// round 10
// speedup vs baseline: 1.0693x; 1.0693x over previous
#include <cuda_runtime.h>

#define HH 128
#define WW 128
#define BB 4
#define CIN 64
#define COUT 64
#define OC1 18

// ---------------- scratch (no allocation allowed) ----------------
__device__ __align__(16) float g_xnhwc[BB*HH*WW*CIN];   // x in NHWC
__device__ __align__(16) float g_off9 [BB*HH*WW*9];     // raw conv1 out, channels 0..8
__device__ __align__(16) float g_wt1p [9*CIN*24];       // conv1 weights [tap][ci][6grp][4] (oc=3g+j, padded)
__device__ __align__(16) float g_wt2  [9*CIN*COUT];     // conv2 weights [k][ci][co]
__device__ float g_stats1[BB*9*2];                      // GN1 sum/sumsq per (b,group)
__device__ float g_stats2[BB*16*2];                     // GN2 sum/sumsq per (b,group)
__device__ float g_sc1[BB*9],  g_sh1[BB*9];             // GN1 per-channel scale/shift
__device__ float g_sc2[BB*COUT], g_sh2[BB*COUT];        // GN2 per-channel scale/shift

// ---------------- K: zero stats ----------------
__global__ void k_zero_stats() {
    int t = threadIdx.x;
    if (t < BB*9*2)  g_stats1[t] = 0.f;
    if (t < BB*16*2) g_stats2[t] = 0.f;
}

// ---------------- K: transpose x NCHW -> NHWC ----------------
__global__ void k_transpose_x(const float* __restrict__ x) {
    __shared__ float tile[32][33];
    int b  = blockIdx.z;
    int p0 = blockIdx.x * 32;
    int c0 = blockIdx.y * 32;
    int tx = threadIdx.x, ty = threadIdx.y;   // 32 x 8
    const float* xb = x + (size_t)b*CIN*HH*WW;
    #pragma unroll
    for (int i = 0; i < 32; i += 8)
        tile[ty+i][tx] = xb[(c0+ty+i)*(HH*WW) + p0 + tx];
    __syncthreads();
    float* ob = g_xnhwc + (size_t)b*HH*WW*CIN;
    #pragma unroll
    for (int i = 0; i < 32; i += 8)
        ob[(size_t)(p0+ty+i)*CIN + c0 + tx] = tile[tx][ty+i];
}

// ---------------- K: prep weights ----------------
__global__ void k_prep_w(const float* __restrict__ w_off, const float* __restrict__ w_dsc) {
    int t = blockIdx.x*blockDim.x + threadIdx.x;
    // g_wt1p: [tap][ci][g][4] with oc = 3g+j (j<3), pad j==3
    if (t < 9*CIN*24) {
        int tap = t / (CIN*24); int r = t % (CIN*24);
        int ci = r / 24; int gj = r % 24;
        int g = gj >> 2, j = gj & 3;
        int oc = g*3 + j;
        float v = 0.f;
        if (j < 3 && oc < OC1)
            v = w_off[oc*(CIN*9) + ci*9 + tap];        // w_off (18,64,3,3)
        g_wt1p[t] = v;
    }
    if (t < 9*CIN*COUT) {
        int k = t / (CIN*COUT); int r = t % (CIN*COUT);
        int ci = r / COUT; int co = r % COUT;
        g_wt2[t] = w_dsc[co*(CIN*9) + ci*9 + k];       // w_dsc (64,64,9,1) -> [k][ci][co]
    }
}

// ---------------- K: conv1 3x3 (64->18) + GN1 stats, ci-split x2 ----------------
// grid: B*H (full 128-px rows), 384 threads (12 warps)
// tx(0..31)->4px, ocg=(ty>>1)(0..5)->3oc, cih=(ty&1)->32-ci half
__global__ __launch_bounds__(384) void k_conv1(const float* __restrict__ b_off) {
    __shared__ __align__(16) float xs [CIN*132];     // [ci][i], i=0..129 <-> w = i-1
    __shared__ __align__(16) float wsp[3*CIN*24];    // [dx][ci][6grp][4]; reused as reduction buf
    __shared__ float ssum[9], ssq[9];
    int t = threadIdx.x;
    int tx  = t & 31;
    int ty  = t >> 5;        // 0..11
    int ocg = ty >> 1;       // 0..5 (warp-uniform)
    int cih = ty & 1;        // 0/1  (warp-uniform)
    int blk = blockIdx.x;
    int h   = blk & (HH-1);
    int b   = blk >> 7;
    if (t < 9) { ssum[t] = 0.f; ssq[t] = 0.f; }

    float acc[4][3];
    #pragma unroll
    for (int p=0;p<4;p++)
        #pragma unroll
        for (int j=0;j<3;j++) acc[p][j]=0.f;

    const float* xb = g_xnhwc + (size_t)b*(HH*WW*CIN);
    int ci0 = cih * 32;

    for (int dy = 0; dy < 3; dy++) {
        int y = h + dy - 1;
        __syncthreads();
        // stage one input row (130 positions x 64 ci), zero-padded
        for (int idx = t; idx < 130*16; idx += 384) {
            int pp = idx >> 4;       // i = pp, w = pp-1
            int q  = idx & 15;
            int w  = pp - 1;
            float4 v = make_float4(0.f,0.f,0.f,0.f);
            if ((unsigned)y < HH && (unsigned)w < WW)
                v = *(const float4*)(xb + ((size_t)y*WW + w)*CIN + q*4);
            xs[(q*4+0)*132 + pp] = v.x;
            xs[(q*4+1)*132 + pp] = v.y;
            xs[(q*4+2)*132 + pp] = v.z;
            xs[(q*4+3)*132 + pp] = v.w;
        }
        // stage padded weights for this dy's 3 taps: contiguous [dx][ci][24]
        {
            const float4* wsrc = (const float4*)(g_wt1p + dy*3*CIN*24);
            float4* wdst = (float4*)wsp;
            for (int idx = t; idx < 3*CIN*6; idx += 384) wdst[idx] = wsrc[idx];
        }
        __syncthreads();
        #pragma unroll 2
        for (int cc = 0; cc < 32; cc++) {
            int ci = ci0 + cc;
            const float4* ap = (const float4*)(xs + ci*132 + tx*4);
            float4 A0 = ap[0], A1 = ap[1];
            float af[8] = {A0.x,A0.y,A0.z,A0.w,A1.x,A1.y,A1.z,A1.w};
            #pragma unroll
            for (int dx = 0; dx < 3; dx++) {
                float4 wv = *(const float4*)(wsp + (dx*CIN + ci)*24 + ocg*4);  // broadcast
                #pragma unroll
                for (int p = 0; p < 4; p++) {
                    float a = af[p+dx];
                    acc[p][0] += a*wv.x;
                    acc[p][1] += a*wv.y;
                    acc[p][2] += a*wv.z;
                }
            }
        }
    }
    __syncthreads();
    // cross-half reduction: half 1 parks in wsp (no longer needed), half 0 accumulates
    float* red = wsp;
    if (cih == 1) {
        int base = (ocg*32 + tx)*12;
        #pragma unroll
        for (int p = 0; p < 4; p++)
            #pragma unroll
            for (int j = 0; j < 3; j++)
                red[base + p*3 + j] = acc[p][j];
    }
    __syncthreads();
    if (cih == 0) {
        int base = (ocg*32 + tx)*12;
        #pragma unroll
        for (int p = 0; p < 4; p++)
            #pragma unroll
            for (int j = 0; j < 3; j++)
                acc[p][j] += red[base + p*3 + j];
        // epilogue: bias, store first 9 channels, GN1 stats (group = oc>>1)
        #pragma unroll
        for (int j = 0; j < 3; j++) {
            int oc = ocg*3 + j;
            float bia = b_off[oc];
            float s = 0.f, sq = 0.f;
            #pragma unroll
            for (int p = 0; p < 4; p++) {
                float r = acc[p][j] + bia;
                s += r; sq += r*r;
                if (oc < 9)
                    g_off9[(((size_t)b*HH + h)*WW + (tx*4 + p))*9 + oc] = r;
            }
            atomicAdd(&ssum[oc>>1], s);
            atomicAdd(&ssq [oc>>1], sq);
        }
    }
    __syncthreads();
    if (t < 9) {
        atomicAdd(&g_stats1[(b*9 + t)*2 + 0], ssum[t]);
        atomicAdd(&g_stats1[(b*9 + t)*2 + 1], ssq[t]);
    }
}

// ---------------- K: finalize GN1 ----------------
__global__ void k_finalize1(const float* __restrict__ g_gn_off, const float* __restrict__ b_gn_off) {
    int t = threadIdx.x;
    if (t >= BB*9) return;
    int b = t / 9, c = t % 9, g = c >> 1;
    float N  = 2.f*HH*WW;
    float mu = g_stats1[(b*9+g)*2+0] / N;
    float var= g_stats1[(b*9+g)*2+1] / N - mu*mu;
    float inv= rsqrtf(var + 1e-5f);
    float sc = g_gn_off[c] * inv;
    g_sc1[t] = sc;
    g_sh1[t] = b_gn_off[c] - mu * sc;
}

// ---------------- K: main fused (round-6 proven: 16x16, 4px x 4co, unroll 2) ----------------
__global__ __launch_bounds__(256) void k_main(const float* __restrict__ b_dsc, float* __restrict__ out) {
    __shared__ __align__(16) float S [CIN*68];    // samples [ci][px(68 pad)]
    __shared__ __align__(16) float Wc[CIN*COUT];  // weight chunk [ci][co]
    __shared__ int   cy0[9*64];
    __shared__ float cwy[9*64];
    __shared__ float sgrp[32];

    int t    = threadIdx.x;
    int blk  = blockIdx.x;
    int half = blk & 1;
    int h    = (blk >> 1) & (HH-1);
    int b    = blk >> 8;
    int w0   = half * 64;

    if (t < 32) sgrp[t] = 0.f;

    // ---- prologue: per-pixel offsets -> tanh -> cumsum -> coords ----
    if (t < 64) {
        int px = t;
        int w  = w0 + px;
        const float* op = g_off9 + (((size_t)b*HH + h)*WW + w)*9;
        float y[9];
        #pragma unroll
        for (int c = 0; c < 9; c++)
            y[c] = tanhf(op[c]*g_sc1[b*9+c] + g_sh1[b*9+c]);
        float o[9];
        o[4]=0.f;
        o[3]=y[3]; o[2]=y[2]+o[3]; o[1]=y[1]+o[2]; o[0]=y[0]+o[1];
        o[5]=y[5]; o[6]=o[5]+y[6]; o[7]=o[6]+y[7]; o[8]=o[7]+y[8];
        #pragma unroll
        for (int k = 0; k < 9; k++) {
            float yc  = fminf(fmaxf((float)h + o[k], 0.f), (float)(HH-1));
            float y0f = floorf(yc);
            cy0[k*64+px] = (int)y0f;
            cwy[k*64+px] = yc - y0f;
        }
    }

    int tx = t & 15, ty = t >> 4;
    float acc[4][4];
    #pragma unroll
    for (int i=0;i<4;i++)
        #pragma unroll
        for (int j=0;j<4;j++) acc[i][j]=0.f;

    int spx = t >> 2;            // sampling: one px per 4 threads
    int c4  = (t & 3) * 16;      // each thread: 16 channels
    const float* xb = g_xnhwc + (size_t)b*(HH*WW*CIN);

    for (int k = 0; k < 9; k++) {
        __syncthreads();
        // stage weight chunk [64ci][64co] (coalesced, pre-transposed)
        {
            const float4* wsrc = (const float4*)(g_wt2 + k*CIN*COUT);
            float4* wdst = (float4*)Wc;
            #pragma unroll
            for (int i = 0; i < 4; i++)
                wdst[t + i*256] = wsrc[t + i*256];
        }
        // build sample chunk: vertical 2-point lerp (x-coord is exact integer)
        {
            int w  = w0 + spx;
            int x0 = min(max(w + k - 4, 0), WW-1);
            int y0 = cy0[k*64 + spx];
            float wy = cwy[k*64 + spx];
            int y1 = min(y0 + 1, HH-1);
            const float* p0 = xb + ((size_t)y0*WW + x0)*CIN + c4;
            const float* p1 = xb + ((size_t)y1*WW + x0)*CIN + c4;
            #pragma unroll
            for (int q = 0; q < 4; q++) {
                float4 v0 = *(const float4*)(p0 + q*4);
                float4 v1 = *(const float4*)(p1 + q*4);
                int ci = c4 + q*4;
                S[(ci+0)*68 + spx] = v0.x + wy*(v1.x - v0.x);
                S[(ci+1)*68 + spx] = v0.y + wy*(v1.y - v0.y);
                S[(ci+2)*68 + spx] = v0.z + wy*(v1.z - v0.z);
                S[(ci+3)*68 + spx] = v0.w + wy*(v1.w - v0.w);
            }
        }
        __syncthreads();
        // SGEMM accumulate over this 64-ci chunk: 2 LDS.128 + 16 FFMA per ci
        #pragma unroll 2
        for (int ci = 0; ci < CIN; ci++) {
            float4 av = *(const float4*)(S + ci*68 + ty*4);     // broadcast
            float4 bb = *(const float4*)(Wc + ci*COUT + tx*4);
            acc[0][0]+=av.x*bb.x; acc[0][1]+=av.x*bb.y; acc[0][2]+=av.x*bb.z; acc[0][3]+=av.x*bb.w;
            acc[1][0]+=av.y*bb.x; acc[1][1]+=av.y*bb.y; acc[1][2]+=av.y*bb.z; acc[1][3]+=av.y*bb.w;
            acc[2][0]+=av.z*bb.x; acc[2][1]+=av.z*bb.y; acc[2][2]+=av.z*bb.z; acc[2][3]+=av.z*bb.w;
            acc[3][0]+=av.w*bb.x; acc[3][1]+=av.w*bb.y; acc[3][2]+=av.w*bb.z; acc[3][3]+=av.w*bb.w;
        }
    }
    __syncthreads();
    // epilogue: bias, raw store (NCHW), GN2 stats (co group == tx)
    float4 bia = *(const float4*)(b_dsc + tx*4);
    float s = 0.f, sq = 0.f;
    #pragma unroll
    for (int i = 0; i < 4; i++) {
        int w = w0 + ty*4 + i;
        float r0 = acc[i][0] + bia.x;
        float r1 = acc[i][1] + bia.y;
        float r2 = acc[i][2] + bia.z;
        float r3 = acc[i][3] + bia.w;
        out[(((size_t)b*COUT + tx*4+0)*HH + h)*WW + w] = r0;
        out[(((size_t)b*COUT + tx*4+1)*HH + h)*WW + w] = r1;
        out[(((size_t)b*COUT + tx*4+2)*HH + h)*WW + w] = r2;
        out[(((size_t)b*COUT + tx*4+3)*HH + h)*WW + w] = r3;
        s  += r0+r1+r2+r3;
        sq += r0*r0 + r1*r1 + r2*r2 + r3*r3;
    }
    atomicAdd(&sgrp[tx*2+0], s);
    atomicAdd(&sgrp[tx*2+1], sq);
    __syncthreads();
    if (t < 32) atomicAdd(&g_stats2[b*32 + t], sgrp[t]);
}

// ---------------- K: finalize GN2 ----------------
__global__ void k_finalize2(const float* __restrict__ g_gn, const float* __restrict__ b_gn) {
    int t = threadIdx.x;
    if (t >= BB*COUT) return;
    int b = t >> 6, co = t & 63, g = co >> 2;
    float N  = 4.f*HH*WW;
    float mu = g_stats2[(b*16+g)*2+0] / N;
    float var= g_stats2[(b*16+g)*2+1] / N - mu*mu;
    float inv= rsqrtf(var + 1e-5f);
    float sc = g_gn[co] * inv;
    g_sc2[t] = sc;
    g_sh2[t] = b_gn[co] - mu * sc;
}

// ---------------- K: normalize + relu in place ----------------
__global__ void k_norm_relu(float* __restrict__ out) {
    int idx = blockIdx.x*blockDim.x + threadIdx.x;   // float4 index
    int e  = idx << 2;
    int bc = e >> 14;                                 // b*64+co
    float sc = g_sc2[bc], sh = g_sh2[bc];
    float4 v = ((float4*)out)[idx];
    v.x = fmaxf(v.x*sc + sh, 0.f);
    v.y = fmaxf(v.y*sc + sh, 0.f);
    v.z = fmaxf(v.z*sc + sh, 0.f);
    v.w = fmaxf(v.w*sc + sh, 0.f);
    ((float4*)out)[idx] = v;
}

// ---------------- launch ----------------
extern "C" void kernel_launch(void* const* d_in, const int* in_sizes, int n_in,
                              void* d_out, int out_size) {
    const float* x        = (const float*)d_in[0];
    const float* w_off    = (const float*)d_in[1];
    const float* b_off    = (const float*)d_in[2];
    const float* g_gn_off = (const float*)d_in[3];
    const float* b_gn_off = (const float*)d_in[4];
    const float* w_dsc    = (const float*)d_in[5];
    const float* b_dsc    = (const float*)d_in[6];
    const float* g_gn     = (const float*)d_in[7];
    const float* b_gn     = (const float*)d_in[8];
    float* out = (float*)d_out;

    k_zero_stats<<<1,128>>>();
    k_transpose_x<<<dim3(512,2,4), dim3(32,8)>>>(x);
    k_prep_w<<<144,256>>>(w_off, w_dsc);
    k_conv1<<<BB*HH, 384>>>(b_off);
    k_finalize1<<<1,64>>>(g_gn_off, b_gn_off);
    k_main<<<BB*HH*2, 256>>>(b_dsc, out);
    k_finalize2<<<1,256>>>(g_gn, b_gn);
    k_norm_relu<<<4096,256>>>(out);
}

// round 12
// speedup vs baseline: 1.1237x; 1.0509x over previous
#include <cuda_runtime.h>

#define HH 128
#define WW 128
#define BB 4
#define CIN 64
#define COUT 64
#define OC1 18

// ---------------- scratch (no allocation allowed) ----------------
__device__ __align__(16) float g_xnhwc[BB*HH*WW*CIN];   // x in NHWC (written by conv1)
__device__ __align__(16) float g_off9 [BB*HH*WW*9];     // raw conv1 out, channels 0..8
__device__ __align__(16) float g_wt1p [9*CIN*24];       // conv1 weights [tap][ci][6grp][4] (oc=3g+j, padded)
__device__ __align__(16) float g_wt2  [9*CIN*COUT];     // conv2 weights [k][ci][co]
__device__ float g_stats1[BB*9*2];                      // GN1 sum/sumsq per (b,group)
__device__ float g_stats2[BB*16*2];                     // GN2 sum/sumsq per (b,group)

// ---------------- K: prep weights (+ zero stats) ----------------
__global__ void k_prep_w(const float* __restrict__ w_off, const float* __restrict__ w_dsc) {
    int t = blockIdx.x*blockDim.x + threadIdx.x;
    if (blockIdx.x == 0) {
        if (threadIdx.x < BB*9*2)  g_stats1[threadIdx.x] = 0.f;
        if (threadIdx.x < BB*16*2) g_stats2[threadIdx.x] = 0.f;
    }
    // g_wt1p: [tap][ci][g][4] with oc = 3g+j (j<3), pad j==3
    if (t < 9*CIN*24) {
        int tap = t / (CIN*24); int r = t % (CIN*24);
        int ci = r / 24; int gj = r % 24;
        int g = gj >> 2, j = gj & 3;
        int oc = g*3 + j;
        float v = 0.f;
        if (j < 3 && oc < OC1)
            v = w_off[oc*(CIN*9) + ci*9 + tap];        // w_off (18,64,3,3)
        g_wt1p[t] = v;
    }
    if (t < 9*CIN*COUT) {
        int k = t / (CIN*COUT); int r = t % (CIN*COUT);
        int ci = r / COUT; int co = r % COUT;
        g_wt2[t] = w_dsc[co*(CIN*9) + ci*9 + k];       // w_dsc (64,64,9,1) -> [k][ci][co]
    }
}

// ---------------- K: conv1 3x3 (64->18) + GN1 stats + NHWC emit, ci-split x2 ----------------
// grid: B*H (full 128-px rows), 384 threads (12 warps)
// tx(0..31)->4px, ocg=(ty>>1)(0..5)->3oc, cih=(ty&1)->32-ci half
// Reads x in NCHW directly; emits the NHWC copy of row h from smem (dy==1).
__global__ __launch_bounds__(384) void k_conv1(const float* __restrict__ x,
                                               const float* __restrict__ b_off) {
    __shared__ __align__(16) float xs [CIN*132];     // [ci][i], i=0..129 <-> w = i-1
    __shared__ __align__(16) float wsp[3*CIN*24];    // [dx][ci][6grp][4]; reused as reduction buf
    __shared__ float ssum[9], ssq[9];
    int t = threadIdx.x;
    int tx  = t & 31;
    int ty  = t >> 5;        // 0..11
    int ocg = ty >> 1;       // 0..5 (warp-uniform)
    int cih = ty & 1;        // 0/1  (warp-uniform)
    int blk = blockIdx.x;
    int h   = blk & (HH-1);
    int b   = blk >> 7;
    if (t < 9) { ssum[t] = 0.f; ssq[t] = 0.f; }

    float acc[4][3];
    #pragma unroll
    for (int p=0;p<4;p++)
        #pragma unroll
        for (int j=0;j<3;j++) acc[p][j]=0.f;

    const float* xb = x + (size_t)b*CIN*HH*WW;   // NCHW
    int ci0 = cih * 32;

    for (int dy = 0; dy < 3; dy++) {
        int y = h + dy - 1;
        __syncthreads();
        // stage one input row from NCHW: per iter one (ci, 4w) float4, coalesced along w
        for (int idx = t; idx < 64*32; idx += 384) {
            int ci = idx >> 5, j = (idx & 31) << 2;   // w = j..j+3 -> i = j+1..j+4
            float4 v = make_float4(0.f,0.f,0.f,0.f);
            if ((unsigned)y < HH)
                v = *(const float4*)(xb + ((size_t)ci*HH + y)*WW + j);
            int base = ci*132 + j + 1;
            xs[base+0] = v.x;
            xs[base+1] = v.y;
            xs[base+2] = v.z;
            xs[base+3] = v.w;
        }
        if (t < 128) xs[(t & 63)*132 + ((t >> 6) ? 129 : 0)] = 0.f;   // halos (w=-1,128) = 0
        // stage padded weights for this dy's 3 taps: contiguous [dx][ci][24]
        {
            const float4* wsrc = (const float4*)(g_wt1p + dy*3*CIN*24);
            float4* wdst = (float4*)wsp;
            for (int idx = t; idx < 3*CIN*6; idx += 384) wdst[idx] = wsrc[idx];
        }
        __syncthreads();
        // emit NHWC copy of row h (once, data already staged)
        if (dy == 1) {
            for (int idx = t; idx < 128*16; idx += 384) {
                int w = idx >> 4, cq = (idx & 15) << 2;
                float4 v;
                v.x = xs[(cq+0)*132 + w+1];
                v.y = xs[(cq+1)*132 + w+1];
                v.z = xs[(cq+2)*132 + w+1];
                v.w = xs[(cq+3)*132 + w+1];
                *(float4*)(g_xnhwc + (((size_t)b*HH + h)*WW + w)*CIN + cq) = v;
            }
        }
        #pragma unroll 2
        for (int cc = 0; cc < 32; cc++) {
            int ci = ci0 + cc;
            const float4* ap = (const float4*)(xs + ci*132 + tx*4);
            float4 A0 = ap[0], A1 = ap[1];
            float af[8] = {A0.x,A0.y,A0.z,A0.w,A1.x,A1.y,A1.z,A1.w};
            #pragma unroll
            for (int dx = 0; dx < 3; dx++) {
                float4 wv = *(const float4*)(wsp + (dx*CIN + ci)*24 + ocg*4);  // broadcast
                #pragma unroll
                for (int p = 0; p < 4; p++) {
                    float a = af[p+dx];
                    acc[p][0] += a*wv.x;
                    acc[p][1] += a*wv.y;
                    acc[p][2] += a*wv.z;
                }
            }
        }
    }
    __syncthreads();
    // cross-half reduction: half 1 parks in wsp (no longer needed), half 0 accumulates
    float* red = wsp;
    if (cih == 1) {
        int base = (ocg*32 + tx)*12;
        #pragma unroll
        for (int p = 0; p < 4; p++)
            #pragma unroll
            for (int j = 0; j < 3; j++)
                red[base + p*3 + j] = acc[p][j];
    }
    __syncthreads();
    if (cih == 0) {
        int base = (ocg*32 + tx)*12;
        #pragma unroll
        for (int p = 0; p < 4; p++)
            #pragma unroll
            for (int j = 0; j < 3; j++)
                acc[p][j] += red[base + p*3 + j];
        // epilogue: bias, store first 9 channels, GN1 stats (group = oc>>1)
        #pragma unroll
        for (int j = 0; j < 3; j++) {
            int oc = ocg*3 + j;
            float bia = b_off[oc];
            float s = 0.f, sq = 0.f;
            #pragma unroll
            for (int p = 0; p < 4; p++) {
                float r = acc[p][j] + bia;
                s += r; sq += r*r;
                if (oc < 9)
                    g_off9[(((size_t)b*HH + h)*WW + (tx*4 + p))*9 + oc] = r;
            }
            atomicAdd(&ssum[oc>>1], s);
            atomicAdd(&ssq [oc>>1], sq);
        }
    }
    __syncthreads();
    if (t < 9) {
        atomicAdd(&g_stats1[(b*9 + t)*2 + 0], ssum[t]);
        atomicAdd(&g_stats1[(b*9 + t)*2 + 1], ssq[t]);
    }
}

// ---------------- K: main fused (GN1 finalize + offsets -> sample -> GEMM -> raw out + GN2 stats) ----------------
// grid: B*H*2 (64-px half-rows), 256 threads: 16x16, 4px x 4co micro-tile (round-6/10 proven)
__global__ __launch_bounds__(256) void k_main(const float* __restrict__ b_dsc,
                                              const float* __restrict__ g_gn_off,
                                              const float* __restrict__ b_gn_off,
                                              float* __restrict__ out) {
    __shared__ __align__(16) float S [CIN*68];    // samples [ci][px(68 pad)]
    __shared__ __align__(16) float Wc[CIN*COUT];  // weight chunk [ci][co]
    __shared__ int   cy0[9*64];
    __shared__ float cwy[9*64];
    __shared__ float sgrp[32];
    __shared__ float sc1s[9], sh1s[9];

    int t    = threadIdx.x;
    int blk  = blockIdx.x;
    int half = blk & 1;
    int h    = (blk >> 1) & (HH-1);
    int b    = blk >> 8;
    int w0   = half * 64;

    // inline GN1 finalize (per block, deterministic)
    if (t < 9) {
        int g = t >> 1;
        float N  = 2.f*HH*WW;
        float mu = g_stats1[(b*9+g)*2+0] / N;
        float var= g_stats1[(b*9+g)*2+1] / N - mu*mu;
        float inv= rsqrtf(var + 1e-5f);
        float sc = g_gn_off[t] * inv;
        sc1s[t] = sc;
        sh1s[t] = b_gn_off[t] - mu * sc;
    }
    if (t < 32) sgrp[t] = 0.f;
    __syncthreads();

    // ---- prologue: per-pixel offsets -> tanh -> cumsum -> coords ----
    if (t < 64) {
        int px = t;
        int w  = w0 + px;
        const float* op = g_off9 + (((size_t)b*HH + h)*WW + w)*9;
        float y[9];
        #pragma unroll
        for (int c = 0; c < 9; c++)
            y[c] = tanhf(op[c]*sc1s[c] + sh1s[c]);
        float o[9];
        o[4]=0.f;
        o[3]=y[3]; o[2]=y[2]+o[3]; o[1]=y[1]+o[2]; o[0]=y[0]+o[1];
        o[5]=y[5]; o[6]=o[5]+y[6]; o[7]=o[6]+y[7]; o[8]=o[7]+y[8];
        #pragma unroll
        for (int k = 0; k < 9; k++) {
            float yc  = fminf(fmaxf((float)h + o[k], 0.f), (float)(HH-1));
            float y0f = floorf(yc);
            cy0[k*64+px] = (int)y0f;
            cwy[k*64+px] = yc - y0f;
        }
    }

    int tx = t & 15, ty = t >> 4;
    float acc[4][4];
    #pragma unroll
    for (int i=0;i<4;i++)
        #pragma unroll
        for (int j=0;j<4;j++) acc[i][j]=0.f;

    int spx = t >> 2;            // sampling: one px per 4 threads
    int c4  = (t & 3) * 16;      // each thread: 16 channels
    const float* xb = g_xnhwc + (size_t)b*(HH*WW*CIN);

    for (int k = 0; k < 9; k++) {
        __syncthreads();
        // stage weight chunk [64ci][64co] (coalesced, pre-transposed)
        {
            const float4* wsrc = (const float4*)(g_wt2 + k*CIN*COUT);
            float4* wdst = (float4*)Wc;
            #pragma unroll
            for (int i = 0; i < 4; i++)
                wdst[t + i*256] = wsrc[t + i*256];
        }
        // build sample chunk: vertical 2-point lerp (x-coord is exact integer)
        {
            int w  = w0 + spx;
            int x0 = min(max(w + k - 4, 0), WW-1);
            int y0 = cy0[k*64 + spx];
            float wy = cwy[k*64 + spx];
            int y1 = min(y0 + 1, HH-1);
            const float* p0 = xb + ((size_t)y0*WW + x0)*CIN + c4;
            const float* p1 = xb + ((size_t)y1*WW + x0)*CIN + c4;
            #pragma unroll
            for (int q = 0; q < 4; q++) {
                float4 v0 = *(const float4*)(p0 + q*4);
                float4 v1 = *(const float4*)(p1 + q*4);
                int ci = c4 + q*4;
                S[(ci+0)*68 + spx] = v0.x + wy*(v1.x - v0.x);
                S[(ci+1)*68 + spx] = v0.y + wy*(v1.y - v0.y);
                S[(ci+2)*68 + spx] = v0.z + wy*(v1.z - v0.z);
                S[(ci+3)*68 + spx] = v0.w + wy*(v1.w - v0.w);
            }
        }
        __syncthreads();
        // SGEMM accumulate over this 64-ci chunk: 2 LDS.128 + 16 FFMA per ci
        #pragma unroll 2
        for (int ci = 0; ci < CIN; ci++) {
            float4 av = *(const float4*)(S + ci*68 + ty*4);     // broadcast
            float4 bb = *(const float4*)(Wc + ci*COUT + tx*4);
            acc[0][0]+=av.x*bb.x; acc[0][1]+=av.x*bb.y; acc[0][2]+=av.x*bb.z; acc[0][3]+=av.x*bb.w;
            acc[1][0]+=av.y*bb.x; acc[1][1]+=av.y*bb.y; acc[1][2]+=av.y*bb.z; acc[1][3]+=av.y*bb.w;
            acc[2][0]+=av.z*bb.x; acc[2][1]+=av.z*bb.y; acc[2][2]+=av.z*bb.z; acc[2][3]+=av.z*bb.w;
            acc[3][0]+=av.w*bb.x; acc[3][1]+=av.w*bb.y; acc[3][2]+=av.w*bb.z; acc[3][3]+=av.w*bb.w;
        }
    }
    __syncthreads();
    // epilogue: bias, raw store (NCHW), GN2 stats (co group == tx)
    float4 bia = *(const float4*)(b_dsc + tx*4);
    float s = 0.f, sq = 0.f;
    #pragma unroll
    for (int i = 0; i < 4; i++) {
        int w = w0 + ty*4 + i;
        float r0 = acc[i][0] + bia.x;
        float r1 = acc[i][1] + bia.y;
        float r2 = acc[i][2] + bia.z;
        float r3 = acc[i][3] + bia.w;
        out[(((size_t)b*COUT + tx*4+0)*HH + h)*WW + w] = r0;
        out[(((size_t)b*COUT + tx*4+1)*HH + h)*WW + w] = r1;
        out[(((size_t)b*COUT + tx*4+2)*HH + h)*WW + w] = r2;
        out[(((size_t)b*COUT + tx*4+3)*HH + h)*WW + w] = r3;
        s  += r0+r1+r2+r3;
        sq += r0*r0 + r1*r1 + r2*r2 + r3*r3;
    }
    atomicAdd(&sgrp[tx*2+0], s);
    atomicAdd(&sgrp[tx*2+1], sq);
    __syncthreads();
    if (t < 32) atomicAdd(&g_stats2[b*32 + t], sgrp[t]);
}

// ---------------- K: GN2 finalize + normalize + relu in place ----------------
// 4096 blocks x 256 threads x float4: each block covers 1/16 of one (b,co) plane
__global__ void k_norm_relu(const float* __restrict__ g_gn, const float* __restrict__ b_gn,
                            float* __restrict__ out) {
    __shared__ float ssc, ssh;
    int blk = blockIdx.x;
    int bc  = blk >> 4;          // b*64 + co
    if (threadIdx.x == 0) {
        int b = bc >> 6, co = bc & 63, g = co >> 2;
        float N  = 4.f*HH*WW;
        float mu = g_stats2[(b*16+g)*2+0] / N;
        float var= g_stats2[(b*16+g)*2+1] / N - mu*mu;
        float inv= rsqrtf(var + 1e-5f);
        float sc = g_gn[co] * inv;
        ssc = sc;
        ssh = b_gn[co] - mu * sc;
    }
    __syncthreads();
    float sc = ssc, sh = ssh;
    int idx = blk*256 + threadIdx.x;   // float4 index
    float4 v = ((float4*)out)[idx];
    v.x = fmaxf(v.x*sc + sh, 0.f);
    v.y = fmaxf(v.y*sc + sh, 0.f);
    v.z = fmaxf(v.z*sc + sh, 0.f);
    v.w = fmaxf(v.w*sc + sh, 0.f);
    ((float4*)out)[idx] = v;
}

// ---------------- launch ----------------
extern "C" void kernel_launch(void* const* d_in, const int* in_sizes, int n_in,
                              void* d_out, int out_size) {
    const float* x        = (const float*)d_in[0];
    const float* w_off    = (const float*)d_in[1];
    const float* b_off    = (const float*)d_in[2];
    const float* g_gn_off = (const float*)d_in[3];
    const float* b_gn_off = (const float*)d_in[4];
    const float* w_dsc    = (const float*)d_in[5];
    const float* b_dsc    = (const float*)d_in[6];
    const float* g_gn     = (const float*)d_in[7];
    const float* b_gn     = (const float*)d_in[8];
    float* out = (float*)d_out;

    k_prep_w<<<144,256>>>(w_off, w_dsc);
    k_conv1<<<BB*HH, 384>>>(x, b_off);
    k_main<<<BB*HH*2, 256>>>(b_dsc, g_gn_off, b_gn_off, out);
    k_norm_relu<<<4096,256>>>(g_gn, b_gn, out);
}